// round 1
// baseline (speedup 1.0000x reference)
#include <cuda_runtime.h>

#define SQ 512      // sequence length (i/j/s axis)
#define NSEQ 512    // n axis
#define CM 64
#define CZ 128
#define NH 8
#define EPS 1e-5f

// Scratch (device globals: allocation-free)
__device__ float g_w[(size_t)SQ * NH * SQ];       // bias logits -> softmax weights [i][h][j]
__device__ float g_v[(size_t)SQ * NSEQ * CM];     // v   [(s*512+n)*64 + c]
__device__ float g_g[(size_t)SQ * NSEQ * CM];     // g   [(s*512+n)*64 + c]
__device__ float g_o[(size_t)SQ * NSEQ * CM];     // o   [(i*512+n)*64 + c]

__device__ __forceinline__ float warp_sum(float v) {
#pragma unroll
    for (int o = 16; o > 0; o >>= 1) v += __shfl_xor_sync(0xffffffffu, v, o);
    return v;
}
__device__ __forceinline__ float warp_max(float v) {
#pragma unroll
    for (int o = 16; o > 0; o >>= 1) v = fmaxf(v, __shfl_xor_sync(0xffffffffu, v, o));
    return v;
}

// ---------------------------------------------------------------------------
// Kernel 1: b[i,h,j] = LN(z[i,j,:]) . W_b[h,:]   (one warp per (i,j) row)
// ---------------------------------------------------------------------------
__global__ __launch_bounds__(256) void bias_ln_kernel(
    const float* __restrict__ z, const float* __restrict__ lnw,
    const float* __restrict__ lnb, const float* __restrict__ Wb)
{
    __shared__ float sWb[NH * CZ];
    int tid = threadIdx.x;
#pragma unroll
    for (int i = tid; i < NH * CZ; i += 256) sWb[i] = Wb[i];
    __syncthreads();

    int warp = tid >> 5, lane = tid & 31;
    size_t row = (size_t)blockIdx.x * 8 + warp;   // 0..262143
    const float* zr = z + row * CZ;
    float4 x = *(const float4*)(zr + lane * 4);

    float s = warp_sum(x.x + x.y + x.z + x.w);
    float mu = s * (1.0f / CZ);
    float d0 = x.x - mu, d1 = x.y - mu, d2 = x.z - mu, d3 = x.w - mu;
    float q = warp_sum(d0 * d0 + d1 * d1 + d2 * d2 + d3 * d3);
    float rs = rsqrtf(q * (1.0f / CZ) + EPS);

    int c = lane * 4;
    float n0 = d0 * rs * __ldg(lnw + c + 0) + __ldg(lnb + c + 0);
    float n1 = d1 * rs * __ldg(lnw + c + 1) + __ldg(lnb + c + 1);
    float n2 = d2 * rs * __ldg(lnw + c + 2) + __ldg(lnb + c + 2);
    float n3 = d3 * rs * __ldg(lnw + c + 3) + __ldg(lnb + c + 3);

    int i = (int)(row >> 9), j = (int)(row & 511);
    float* dst = g_w + (size_t)i * (NH * SQ) + j;
#pragma unroll
    for (int h = 0; h < NH; ++h) {
        float4 wb = *(const float4*)(sWb + h * CZ + c);
        float p = warp_sum(n0 * wb.x + n1 * wb.y + n2 * wb.z + n3 * wb.w);
        if (lane == 0) dst[h * SQ] = p;
    }
}

// ---------------------------------------------------------------------------
// Kernel 2: softmax over j (in place), one block per (i,h) row of 512
// ---------------------------------------------------------------------------
__global__ __launch_bounds__(256) void softmax_kernel()
{
    float* row = g_w + (size_t)blockIdx.x * SQ;
    __shared__ float sred[8];
    int tid = threadIdx.x, lane = tid & 31, warp = tid >> 5;

    float a = row[tid], b = row[tid + 256];
    float m = warp_max(fmaxf(a, b));
    if (lane == 0) sred[warp] = m;
    __syncthreads();
    float M = sred[0];
#pragma unroll
    for (int w = 1; w < 8; ++w) M = fmaxf(M, sred[w]);

    float e0 = __expf(a - M), e1 = __expf(b - M);
    float s = warp_sum(e0 + e1);
    __syncthreads();
    if (lane == 0) sred[warp] = s;
    __syncthreads();
    float tot = 0.f;
#pragma unroll
    for (int w = 0; w < 8; ++w) tot += sred[w];
    float inv = 1.0f / tot;
    row[tid] = e0 * inv;
    row[tid + 256] = e1 * inv;
}

// ---------------------------------------------------------------------------
// Kernel 3: fused LN(m) -> v = LN(m) @ Wv^T,  g = sigmoid(LN(m) @ Wg^T)
// Tile: 64 rows x 64 cols, K=64.  Smem: As[64][64] (transposed, LN'd),
// Wvt/Wgt[64][64] transposed. 48KB static total.
// ---------------------------------------------------------------------------
__global__ __launch_bounds__(256) void vg_kernel(
    const float* __restrict__ m, const float* __restrict__ lnw,
    const float* __restrict__ lnb, const float* __restrict__ Wv,
    const float* __restrict__ Wg)
{
    __shared__ float As[64 * 64];
    __shared__ float Wvt[64 * 64];
    __shared__ float Wgt[64 * 64];
    int tid = threadIdx.x;

    // transpose-load weights: Wt[k][c] = W[c][k]; conflict-free scalar stores
#pragma unroll
    for (int it = 0; it < 4; ++it) {
        int idx = it * 256 + tid;
        int c = idx & 63, kq = idx >> 6;
        float4 a = *(const float4*)(Wv + c * 64 + kq * 4);
        Wvt[(kq * 4 + 0) * 64 + c] = a.x;
        Wvt[(kq * 4 + 1) * 64 + c] = a.y;
        Wvt[(kq * 4 + 2) * 64 + c] = a.z;
        Wvt[(kq * 4 + 3) * 64 + c] = a.w;
        float4 b = *(const float4*)(Wg + c * 64 + kq * 4);
        Wgt[(kq * 4 + 0) * 64 + c] = b.x;
        Wgt[(kq * 4 + 1) * 64 + c] = b.y;
        Wgt[(kq * 4 + 2) * 64 + c] = b.z;
        Wgt[(kq * 4 + 3) * 64 + c] = b.w;
    }

    // load 64-row m tile; thread owns row=tid&63, kq = (tid>>6)+4*it  (16 floats)
    int row = tid & 63;
    size_t base = (size_t)blockIdx.x * 64 * CM;
    float vals[16];
    float s = 0.f, q = 0.f;
#pragma unroll
    for (int it = 0; it < 4; ++it) {
        int kq = (tid >> 6) + it * 4;
        float4 a = *(const float4*)(m + base + (size_t)row * CM + kq * 4);
        vals[it * 4 + 0] = a.x; vals[it * 4 + 1] = a.y;
        vals[it * 4 + 2] = a.z; vals[it * 4 + 3] = a.w;
        s += a.x + a.y + a.z + a.w;
        q += a.x * a.x + a.y * a.y + a.z * a.z + a.w * a.w;
    }
    // cross-thread (4 partials per row) reduction via As scratch
    As[tid] = s;
    As[256 + tid] = q;
    __syncthreads();
    float st = 0.f, qt = 0.f;
#pragma unroll
    for (int p = 0; p < 4; ++p) {
        st += As[row + p * 64];
        qt += As[256 + row + p * 64];
    }
    float mu = st * (1.0f / CM);
    float var = qt * (1.0f / CM) - mu * mu;
    float rs = rsqrtf(var + EPS);
    __syncthreads();   // done reading scratch before overwrite

    // normalize + store transposed As[k][row]
#pragma unroll
    for (int it = 0; it < 4; ++it) {
        int kq = (tid >> 6) + it * 4;
#pragma unroll
        for (int t = 0; t < 4; ++t) {
            int k = kq * 4 + t;
            float xn = (vals[it * 4 + t] - mu) * rs * __ldg(lnw + k) + __ldg(lnb + k);
            As[k * 64 + row] = xn;
        }
    }
    __syncthreads();

    int tx = tid & 15, ty = tid >> 4;
    float av[4][4], ag[4][4];
#pragma unroll
    for (int r = 0; r < 4; ++r)
#pragma unroll
        for (int c = 0; c < 4; ++c) { av[r][c] = 0.f; ag[r][c] = 0.f; }

#pragma unroll
    for (int k = 0; k < 64; ++k) {
        float4 a = *(const float4*)(As + k * 64 + ty * 4);
        float4 wv = *(const float4*)(Wvt + k * 64 + tx * 4);
        float4 wg = *(const float4*)(Wgt + k * 64 + tx * 4);
        float ar[4] = {a.x, a.y, a.z, a.w};
        float wvr[4] = {wv.x, wv.y, wv.z, wv.w};
        float wgr[4] = {wg.x, wg.y, wg.z, wg.w};
#pragma unroll
        for (int r = 0; r < 4; ++r)
#pragma unroll
            for (int c = 0; c < 4; ++c) {
                av[r][c] = fmaf(ar[r], wvr[c], av[r][c]);
                ag[r][c] = fmaf(ar[r], wgr[c], ag[r][c]);
            }
    }
#pragma unroll
    for (int r = 0; r < 4; ++r) {
        int orow = ty * 4 + r;
        size_t addr = base + (size_t)orow * CM + tx * 4;
        *(float4*)(g_v + addr) = make_float4(av[r][0], av[r][1], av[r][2], av[r][3]);
        float4 gg;
        gg.x = 1.0f / (1.0f + __expf(-ag[r][0]));
        gg.y = 1.0f / (1.0f + __expf(-ag[r][1]));
        gg.z = 1.0f / (1.0f + __expf(-ag[r][2]));
        gg.w = 1.0f / (1.0f + __expf(-ag[r][3]));
        *(float4*)(g_g + addr) = gg;
    }
}

// ---------------------------------------------------------------------------
// Kernel 4: per-head GEMM  o_h[i, nd] = sum_j w[i,h,j] * v[j, nd(h)]
// M=512, N=4096(cols nd=n*8+d), K=512 per head. 128x128x16 tiles, 8x8 microtile.
// ---------------------------------------------------------------------------
__global__ __launch_bounds__(256) void pwa_gemm_kernel()
{
    __shared__ float As[16 * 128];
    __shared__ float Bs[16 * 128];
    int h = blockIdx.z;
    int i0 = blockIdx.y * 128;
    int c0 = blockIdx.x * 128;   // nd column base
    int tid = threadIdx.x;
    int tx = tid & 15, ty = tid >> 4;

    float acc[8][8];
#pragma unroll
    for (int r = 0; r < 8; ++r)
#pragma unroll
        for (int c = 0; c < 8; ++c) acc[r][c] = 0.f;

    for (int k0 = 0; k0 < SQ; k0 += 16) {
#pragma unroll
        for (int it = 0; it < 2; ++it) {
            int idx = it * 256 + tid;
            {   // A tile (w): row=i, K=j contiguous; store transposed As[k][row]
                int row = idx & 127, kq = idx >> 7;
                float4 a = *(const float4*)(g_w + (size_t)(i0 + row) * (NH * SQ)
                                            + h * SQ + k0 + kq * 4);
                As[(kq * 4 + 0) * 128 + row] = a.x;
                As[(kq * 4 + 1) * 128 + row] = a.y;
                As[(kq * 4 + 2) * 128 + row] = a.z;
                As[(kq * 4 + 3) * 128 + row] = a.w;
            }
            {   // B tile (v): B(kb, col) with col=nd
                int colq = idx & 31, kb = idx >> 5;
                int col = c0 + colq * 4;
                float4 b = *(const float4*)(g_v + (size_t)(k0 + kb) * (NSEQ * CM)
                                            + (size_t)(col >> 3) * CM + h * 8 + (col & 7));
                *(float4*)(Bs + kb * 128 + colq * 4) = b;
            }
        }
        __syncthreads();
#pragma unroll
        for (int k = 0; k < 16; ++k) {
            float4 a0 = *(const float4*)(As + k * 128 + ty * 4);
            float4 a1 = *(const float4*)(As + k * 128 + 64 + ty * 4);
            float4 b0 = *(const float4*)(Bs + k * 128 + tx * 4);
            float4 b1 = *(const float4*)(Bs + k * 128 + 64 + tx * 4);
            float a[8] = {a0.x, a0.y, a0.z, a0.w, a1.x, a1.y, a1.z, a1.w};
            float b[8] = {b0.x, b0.y, b0.z, b0.w, b1.x, b1.y, b1.z, b1.w};
#pragma unroll
            for (int r = 0; r < 8; ++r)
#pragma unroll
                for (int c = 0; c < 8; ++c)
                    acc[r][c] = fmaf(a[r], b[c], acc[r][c]);
        }
        __syncthreads();
    }

#pragma unroll
    for (int rh = 0; rh < 2; ++rh)
#pragma unroll
        for (int rr = 0; rr < 4; ++rr) {
            int i = i0 + rh * 64 + ty * 4 + rr;
#pragma unroll
            for (int ch = 0; ch < 2; ++ch) {
                int col = c0 + ch * 64 + tx * 4;
                float4 v4 = make_float4(acc[rh * 4 + rr][ch * 4 + 0],
                                        acc[rh * 4 + rr][ch * 4 + 1],
                                        acc[rh * 4 + rr][ch * 4 + 2],
                                        acc[rh * 4 + rr][ch * 4 + 3]);
                *(float4*)(g_o + (size_t)i * (NSEQ * CM)
                           + (size_t)(col >> 3) * CM + h * 8 + (col & 7)) = v4;
            }
        }
}

// ---------------------------------------------------------------------------
// Kernel 5: out = (g .* o) @ Wout^T   (gating fused into A-tile load)
// Tile: 128 rows x 64 cols, K=64. Smem 48KB static.
// ---------------------------------------------------------------------------
__global__ __launch_bounds__(256) void out_kernel(
    const float* __restrict__ Wout, float* __restrict__ out)
{
    __shared__ float As[64 * 128];
    __shared__ float Wt[64 * 64];
    int tid = threadIdx.x;
#pragma unroll
    for (int it = 0; it < 4; ++it) {
        int idx = it * 256 + tid;
        int c = idx & 63, kq = idx >> 6;
        float4 a = *(const float4*)(Wout + c * 64 + kq * 4);
        Wt[(kq * 4 + 0) * 64 + c] = a.x;
        Wt[(kq * 4 + 1) * 64 + c] = a.y;
        Wt[(kq * 4 + 2) * 64 + c] = a.z;
        Wt[(kq * 4 + 3) * 64 + c] = a.w;
    }

    int row = tid & 127;
    size_t base = (size_t)blockIdx.x * 128 * CM;
#pragma unroll
    for (int it = 0; it < 8; ++it) {
        int kq = (tid >> 7) + it * 2;
        size_t addr = base + (size_t)row * CM + kq * 4;
        float4 gg = *(const float4*)(g_g + addr);
        float4 oo = *(const float4*)(g_o + addr);
        As[(kq * 4 + 0) * 128 + row] = gg.x * oo.x;
        As[(kq * 4 + 1) * 128 + row] = gg.y * oo.y;
        As[(kq * 4 + 2) * 128 + row] = gg.z * oo.z;
        As[(kq * 4 + 3) * 128 + row] = gg.w * oo.w;
    }
    __syncthreads();

    int tx = tid & 15, ty = tid >> 4;
    float acc[8][4];
#pragma unroll
    for (int r = 0; r < 8; ++r)
#pragma unroll
        for (int c = 0; c < 4; ++c) acc[r][c] = 0.f;

#pragma unroll
    for (int k = 0; k < 64; ++k) {
        float4 a0 = *(const float4*)(As + k * 128 + ty * 4);
        float4 a1 = *(const float4*)(As + k * 128 + 64 + ty * 4);
        float4 w = *(const float4*)(Wt + k * 64 + tx * 4);
        float a[8] = {a0.x, a0.y, a0.z, a0.w, a1.x, a1.y, a1.z, a1.w};
        float wr[4] = {w.x, w.y, w.z, w.w};
#pragma unroll
        for (int r = 0; r < 8; ++r)
#pragma unroll
            for (int c = 0; c < 4; ++c)
                acc[r][c] = fmaf(a[r], wr[c], acc[r][c]);
    }
#pragma unroll
    for (int rh = 0; rh < 2; ++rh)
#pragma unroll
        for (int rr = 0; rr < 4; ++rr) {
            int orow = rh * 64 + ty * 4 + rr;
            float4 v4 = make_float4(acc[rh * 4 + rr][0], acc[rh * 4 + rr][1],
                                    acc[rh * 4 + rr][2], acc[rh * 4 + rr][3]);
            *(float4*)(out + base + (size_t)orow * CM + tx * 4) = v4;
        }
}

// ---------------------------------------------------------------------------
extern "C" void kernel_launch(void* const* d_in, const int* in_sizes, int n_in,
                              void* d_out, int out_size)
{
    const float* m    = (const float*)d_in[0];
    const float* z    = (const float*)d_in[1];
    const float* lnmw = (const float*)d_in[2];
    const float* lnmb = (const float*)d_in[3];
    const float* lnzw = (const float*)d_in[4];
    const float* lnzb = (const float*)d_in[5];
    const float* Wv   = (const float*)d_in[6];
    const float* Wb   = (const float*)d_in[7];
    const float* Wg   = (const float*)d_in[8];
    const float* Wout = (const float*)d_in[9];
    float* out = (float*)d_out;

    bias_ln_kernel<<<SQ * SQ / 8, 256>>>(z, lnzw, lnzb, Wb);
    softmax_kernel<<<SQ * NH, 256>>>();
    vg_kernel<<<SQ * NSEQ / 64, 256>>>(m, lnmw, lnmb, Wv, Wg);
    dim3 gD(NSEQ * 8 / 128, SQ / 128, NH);   // (32, 4, 8)
    pwa_gemm_kernel<<<gD, 256>>>();
    out_kernel<<<SQ * NSEQ / 128, 256>>>(Wout, out);
}

// round 3
// speedup vs baseline: 1.2064x; 1.2064x over previous
#include <cuda_runtime.h>
#include <cstdint>

#define SQ 512
#define NSEQ 512
#define CM 64
#define CZ 128
#define NH 8
#define EPS 1e-5f

// Scratch (device globals: allocation-free)
__device__ float g_w[(size_t)SQ * NH * SQ];        // softmax weights [i][h][j]
__device__ float g_vT[(size_t)CM * NSEQ * SQ];     // [(c*512+n)*512 + j]
__device__ float g_g[(size_t)SQ * NSEQ * CM];      // gate [(s*512+n)*64 + c]
__device__ float g_o2[(size_t)CM * NSEQ * SQ];     // [(c*512+n)*512 + i]

__device__ __forceinline__ float warp_sum(float v) {
#pragma unroll
    for (int o = 16; o > 0; o >>= 1) v += __shfl_xor_sync(0xffffffffu, v, o);
    return v;
}
__device__ __forceinline__ float warp_max(float v) {
#pragma unroll
    for (int o = 16; o > 0; o >>= 1) v = fmaxf(v, __shfl_xor_sync(0xffffffffu, v, o));
    return v;
}

// ---------------------------------------------------------------------------
// Kernel 1: b[i,h,j] = LN(z[i,j,:]) . W_b[h,:]   (one warp per (i,j) row)
// ---------------------------------------------------------------------------
__global__ __launch_bounds__(256) void bias_ln_kernel(
    const float* __restrict__ z, const float* __restrict__ lnw,
    const float* __restrict__ lnb, const float* __restrict__ Wb)
{
    __shared__ float sWb[NH * CZ];
    int tid = threadIdx.x;
#pragma unroll
    for (int i = tid; i < NH * CZ; i += 256) sWb[i] = Wb[i];
    __syncthreads();

    int warp = tid >> 5, lane = tid & 31;
    size_t row = (size_t)blockIdx.x * 8 + warp;
    float4 x = *(const float4*)(z + row * CZ + lane * 4);

    float s = warp_sum(x.x + x.y + x.z + x.w);
    float mu = s * (1.0f / CZ);
    float d0 = x.x - mu, d1 = x.y - mu, d2 = x.z - mu, d3 = x.w - mu;
    float q = warp_sum(d0 * d0 + d1 * d1 + d2 * d2 + d3 * d3);
    float rs = rsqrtf(q * (1.0f / CZ) + EPS);

    int c = lane * 4;
    float n0 = d0 * rs * __ldg(lnw + c + 0) + __ldg(lnb + c + 0);
    float n1 = d1 * rs * __ldg(lnw + c + 1) + __ldg(lnb + c + 1);
    float n2 = d2 * rs * __ldg(lnw + c + 2) + __ldg(lnb + c + 2);
    float n3 = d3 * rs * __ldg(lnw + c + 3) + __ldg(lnb + c + 3);

    int i = (int)(row >> 9), j = (int)(row & 511);
    float* dst = g_w + (size_t)i * (NH * SQ) + j;
#pragma unroll
    for (int h = 0; h < NH; ++h) {
        float4 wb = *(const float4*)(sWb + h * CZ + c);
        float p = warp_sum(n0 * wb.x + n1 * wb.y + n2 * wb.z + n3 * wb.w);
        if (lane == 0) dst[h * SQ] = p;
    }
}

// ---------------------------------------------------------------------------
// Kernel 2: softmax over j (in place), one block per (i,h) row of 512
// ---------------------------------------------------------------------------
__global__ __launch_bounds__(256) void softmax_kernel()
{
    float* row = g_w + (size_t)blockIdx.x * SQ;
    __shared__ float sred[8];
    int tid = threadIdx.x, lane = tid & 31, warp = tid >> 5;

    float a = row[tid], b = row[tid + 256];
    float m = warp_max(fmaxf(a, b));
    if (lane == 0) sred[warp] = m;
    __syncthreads();
    float M = sred[0];
#pragma unroll
    for (int w = 1; w < 8; ++w) M = fmaxf(M, sred[w]);

    float e0 = __expf(a - M), e1 = __expf(b - M);
    float s = warp_sum(e0 + e1);
    __syncthreads();
    if (lane == 0) sred[warp] = s;
    __syncthreads();
    float tot = 0.f;
#pragma unroll
    for (int w = 0; w < 8; ++w) tot += sred[w];
    float inv = 1.0f / tot;
    row[tid] = e0 * inv;
    row[tid + 256] = e1 * inv;
}

// ---------------------------------------------------------------------------
// Kernel 3: fused LN(m) -> vT (transposed), g (gate).
// ---------------------------------------------------------------------------
__global__ __launch_bounds__(256) void vg_kernel(
    const float* __restrict__ m, const float* __restrict__ lnw,
    const float* __restrict__ lnb, const float* __restrict__ Wv,
    const float* __restrict__ Wg)
{
    __shared__ float As[64 * 64];
    __shared__ float Wvt[64 * 64];
    __shared__ float Wgt[64 * 64];
    int tid = threadIdx.x;
    int n = blockIdx.x & 511, s0 = (blockIdx.x >> 9) * 64;

#pragma unroll
    for (int it = 0; it < 4; ++it) {
        int idx = it * 256 + tid;
        int c = idx & 63, kq = idx >> 6;
        float4 a = *(const float4*)(Wv + c * 64 + kq * 4);
        Wvt[(kq * 4 + 0) * 64 + c] = a.x;
        Wvt[(kq * 4 + 1) * 64 + c] = a.y;
        Wvt[(kq * 4 + 2) * 64 + c] = a.z;
        Wvt[(kq * 4 + 3) * 64 + c] = a.w;
        float4 b = *(const float4*)(Wg + c * 64 + kq * 4);
        Wgt[(kq * 4 + 0) * 64 + c] = b.x;
        Wgt[(kq * 4 + 1) * 64 + c] = b.y;
        Wgt[(kq * 4 + 2) * 64 + c] = b.z;
        Wgt[(kq * 4 + 3) * 64 + c] = b.w;
    }

    int row = tid & 63;
    size_t rowbase = ((size_t)(s0 + row) * 512 + n) * CM;
    float vals[16];
    float s = 0.f, q = 0.f;
#pragma unroll
    for (int it = 0; it < 4; ++it) {
        int kq = (tid >> 6) + it * 4;
        float4 a = *(const float4*)(m + rowbase + kq * 4);
        vals[it * 4 + 0] = a.x; vals[it * 4 + 1] = a.y;
        vals[it * 4 + 2] = a.z; vals[it * 4 + 3] = a.w;
        s += a.x + a.y + a.z + a.w;
        q += a.x * a.x + a.y * a.y + a.z * a.z + a.w * a.w;
    }
    As[tid] = s;
    As[256 + tid] = q;
    __syncthreads();
    float st = 0.f, qt = 0.f;
#pragma unroll
    for (int p = 0; p < 4; ++p) {
        st += As[row + p * 64];
        qt += As[256 + row + p * 64];
    }
    float mu = st * (1.0f / CM);
    float var = qt * (1.0f / CM) - mu * mu;
    float rs = rsqrtf(var + EPS);
    __syncthreads();

#pragma unroll
    for (int it = 0; it < 4; ++it) {
        int kq = (tid >> 6) + it * 4;
#pragma unroll
        for (int t = 0; t < 4; ++t) {
            int k = kq * 4 + t;
            As[k * 64 + row] = (vals[it * 4 + t] - mu) * rs * __ldg(lnw + k) + __ldg(lnb + k);
        }
    }
    __syncthreads();

    int tx = tid & 15, ty = tid >> 4;
    float av[4][4], ag[4][4];
#pragma unroll
    for (int r = 0; r < 4; ++r)
#pragma unroll
        for (int c = 0; c < 4; ++c) { av[r][c] = 0.f; ag[r][c] = 0.f; }

#pragma unroll
    for (int k = 0; k < 64; ++k) {
        float4 a = *(const float4*)(As + k * 64 + ty * 4);
        float4 wv = *(const float4*)(Wvt + k * 64 + tx * 4);
        float4 wg = *(const float4*)(Wgt + k * 64 + tx * 4);
        float ar[4] = {a.x, a.y, a.z, a.w};
        float wvr[4] = {wv.x, wv.y, wv.z, wv.w};
        float wgr[4] = {wg.x, wg.y, wg.z, wg.w};
#pragma unroll
        for (int r = 0; r < 4; ++r)
#pragma unroll
            for (int c = 0; c < 4; ++c) {
                av[r][c] = fmaf(ar[r], wvr[c], av[r][c]);
                ag[r][c] = fmaf(ar[r], wgr[c], ag[r][c]);
            }
    }

#pragma unroll
    for (int r = 0; r < 4; ++r) {
        float4 gg;
        gg.x = 1.0f / (1.0f + __expf(-ag[r][0]));
        gg.y = 1.0f / (1.0f + __expf(-ag[r][1]));
        gg.z = 1.0f / (1.0f + __expf(-ag[r][2]));
        gg.w = 1.0f / (1.0f + __expf(-ag[r][3]));
        *(float4*)(g_g + ((size_t)(s0 + ty * 4 + r) * 512 + n) * CM + tx * 4) = gg;
    }
#pragma unroll
    for (int cc = 0; cc < 4; ++cc) {
        int c = tx * 4 + cc;
        float4 v4 = make_float4(av[0][cc], av[1][cc], av[2][cc], av[3][cc]);
        *(float4*)(g_vT + ((size_t)c * 512 + n) * 512 + s0 + ty * 4) = v4;
    }
}

// ---------------------------------------------------------------------------
// Kernel 4: mma.sync TF32 3x-split GEMM per head.
// o2[(c,n), i] = sum_j w[i,h,j] * vT[(c,n), j]
// Block: 128(i) x 128(nd), K-chunk 32, double-buffered smem.
// Warp tile: 32(i) x 64(nd) -> 2 m-tiles x 8 n-tiles of m16n8k8.
// ---------------------------------------------------------------------------
#define PW_PAD 36
#define PW_STGF 18432        // floats per stage (4 arrays of 128*36)
#define PW_SMEMB (2 * PW_STGF * 4)

__device__ __forceinline__ void mma_tf32(float* d, const uint32_t* a,
                                         uint32_t b0, uint32_t b1) {
    asm volatile(
        "mma.sync.aligned.m16n8k8.row.col.f32.tf32.tf32.f32 "
        "{%0,%1,%2,%3}, {%4,%5,%6,%7}, {%8,%9}, {%0,%1,%2,%3};"
        : "+f"(d[0]), "+f"(d[1]), "+f"(d[2]), "+f"(d[3])
        : "r"(a[0]), "r"(a[1]), "r"(a[2]), "r"(a[3]), "r"(b0), "r"(b1));
}
__device__ __forceinline__ float tf32m(float x) {
    return __uint_as_float(__float_as_uint(x) & 0xFFFFE000u);
}
__device__ __forceinline__ uint32_t fu(float x) { return __float_as_uint(x); }

__global__ __launch_bounds__(256, 1) void pwa_mma_kernel()
{
    extern __shared__ float sm[];
    int tid = threadIdx.x, wid = tid >> 5, lane = tid & 31;
    int g = lane >> 2, tg = lane & 3;
    int h = blockIdx.z;
    int i0 = blockIdx.y * 128;
    int nd0 = blockIdx.x * 128;
    const float* Ag = g_w + (size_t)i0 * (NH * SQ) + h * SQ;
    const float* Bg = g_vT + ((size_t)h * 4096 + nd0) * 512;

    int wi = (wid & 3) * 32, wn = (wid >> 2) * 64;

    float acc[2][8][4];
#pragma unroll
    for (int mt = 0; mt < 2; ++mt)
#pragma unroll
        for (int nt = 0; nt < 8; ++nt)
#pragma unroll
            for (int r = 0; r < 4; ++r) acc[mt][nt][r] = 0.f;

    // ---- stage 0 load ----
    {
        float* Ahi = sm;            float* Alo = sm + 4608;
        float* Bhi = sm + 9216;     float* Blo = sm + 13824;
#pragma unroll
        for (int it = 0; it < 4; ++it) {
            int idx = it * 256 + tid;
            int row = idx >> 3, q = idx & 7;
            float4 a = *(const float4*)(Ag + (size_t)row * 4096 + q * 4);
            float4 ahf = make_float4(tf32m(a.x), tf32m(a.y), tf32m(a.z), tf32m(a.w));
            float4 alf = make_float4(tf32m(a.x - ahf.x), tf32m(a.y - ahf.y),
                                     tf32m(a.z - ahf.z), tf32m(a.w - ahf.w));
            *(float4*)(Ahi + row * PW_PAD + q * 4) = ahf;
            *(float4*)(Alo + row * PW_PAD + q * 4) = alf;
            float4 b = *(const float4*)(Bg + (size_t)row * 512 + q * 4);
            float4 bhf = make_float4(tf32m(b.x), tf32m(b.y), tf32m(b.z), tf32m(b.w));
            float4 blf = make_float4(tf32m(b.x - bhf.x), tf32m(b.y - bhf.y),
                                     tf32m(b.z - bhf.z), tf32m(b.w - bhf.w));
            *(float4*)(Bhi + row * PW_PAD + q * 4) = bhf;
            *(float4*)(Blo + row * PW_PAD + q * 4) = blf;
        }
    }
    __syncthreads();

    for (int c = 0; c < 16; ++c) {
        int b = c & 1;
        float4 pa[4], pb[4];
        if (c < 15) {
            int k0 = (c + 1) * 32;
#pragma unroll
            for (int it = 0; it < 4; ++it) {
                int idx = it * 256 + tid;
                int row = idx >> 3, q = idx & 7;
                pa[it] = *(const float4*)(Ag + (size_t)row * 4096 + k0 + q * 4);
                pb[it] = *(const float4*)(Bg + (size_t)row * 512 + k0 + q * 4);
            }
        }
        const float* Ahi = sm + b * PW_STGF;
        const float* Alo = Ahi + 4608;
        const float* Bhi = Ahi + 9216;
        const float* Blo = Ahi + 13824;

#pragma unroll
        for (int kk = 0; kk < 4; ++kk) {
            int kb = kk * 8;
            uint32_t ah[2][4], al[2][4];
#pragma unroll
            for (int mt = 0; mt < 2; ++mt) {
                int r0 = wi + mt * 16 + g;
                ah[mt][0] = fu(Ahi[r0 * PW_PAD + kb + tg]);
                ah[mt][1] = fu(Ahi[(r0 + 8) * PW_PAD + kb + tg]);
                ah[mt][2] = fu(Ahi[r0 * PW_PAD + kb + tg + 4]);
                ah[mt][3] = fu(Ahi[(r0 + 8) * PW_PAD + kb + tg + 4]);
                al[mt][0] = fu(Alo[r0 * PW_PAD + kb + tg]);
                al[mt][1] = fu(Alo[(r0 + 8) * PW_PAD + kb + tg]);
                al[mt][2] = fu(Alo[r0 * PW_PAD + kb + tg + 4]);
                al[mt][3] = fu(Alo[(r0 + 8) * PW_PAD + kb + tg + 4]);
            }
#pragma unroll
            for (int nt = 0; nt < 8; ++nt) {
                int nr = wn + nt * 8 + g;
                uint32_t bh0 = fu(Bhi[nr * PW_PAD + kb + tg]);
                uint32_t bh1 = fu(Bhi[nr * PW_PAD + kb + tg + 4]);
                uint32_t bl0 = fu(Blo[nr * PW_PAD + kb + tg]);
                uint32_t bl1 = fu(Blo[nr * PW_PAD + kb + tg + 4]);
#pragma unroll
                for (int mt = 0; mt < 2; ++mt) {
                    mma_tf32(acc[mt][nt], ah[mt], bh0, bh1);
                    mma_tf32(acc[mt][nt], al[mt], bh0, bh1);
                    mma_tf32(acc[mt][nt], ah[mt], bl0, bl1);
                }
            }
        }
        if (c < 15) {
            float* dAhi = sm + (b ^ 1) * PW_STGF;
            float* dAlo = dAhi + 4608;
            float* dBhi = dAhi + 9216;
            float* dBlo = dAhi + 13824;
#pragma unroll
            for (int it = 0; it < 4; ++it) {
                int idx = it * 256 + tid;
                int row = idx >> 3, q = idx & 7;
                float4 a = pa[it];
                float4 ahf = make_float4(tf32m(a.x), tf32m(a.y), tf32m(a.z), tf32m(a.w));
                float4 alf = make_float4(tf32m(a.x - ahf.x), tf32m(a.y - ahf.y),
                                         tf32m(a.z - ahf.z), tf32m(a.w - ahf.w));
                *(float4*)(dAhi + row * PW_PAD + q * 4) = ahf;
                *(float4*)(dAlo + row * PW_PAD + q * 4) = alf;
                float4 bb = pb[it];
                float4 bhf = make_float4(tf32m(bb.x), tf32m(bb.y), tf32m(bb.z), tf32m(bb.w));
                float4 blf = make_float4(tf32m(bb.x - bhf.x), tf32m(bb.y - bhf.y),
                                         tf32m(bb.z - bhf.z), tf32m(bb.w - bhf.w));
                *(float4*)(dBhi + row * PW_PAD + q * 4) = bhf;
                *(float4*)(dBlo + row * PW_PAD + q * 4) = blf;
            }
        }
        __syncthreads();
    }

    // ---- epilogue: stage C in smem (pad 132), then coalesced gmem stores ----
    float* Cs = sm;
#pragma unroll
    for (int mt = 0; mt < 2; ++mt) {
        int ir = wi + mt * 16 + g;
#pragma unroll
        for (int nt = 0; nt < 8; ++nt) {
            int ndl = wn + nt * 8 + 2 * tg;
            Cs[ndl * 132 + ir]           = acc[mt][nt][0];
            Cs[(ndl + 1) * 132 + ir]     = acc[mt][nt][1];
            Cs[ndl * 132 + ir + 8]       = acc[mt][nt][2];
            Cs[(ndl + 1) * 132 + ir + 8] = acc[mt][nt][3];
        }
    }
    __syncthreads();
    size_t obase = ((size_t)h * 4096 + nd0) * 512 + i0;
#pragma unroll
    for (int it = 0; it < 16; ++it) {
        int idx = it * 256 + tid;
        int ndl = idx >> 5, iq = idx & 31;
        *(float4*)(g_o2 + obase + (size_t)ndl * 512 + iq * 4) =
            *(const float4*)(Cs + ndl * 132 + iq * 4);
    }
}

// ---------------------------------------------------------------------------
// Kernel 5: out = (g .* o) @ Wout^T.
// ---------------------------------------------------------------------------
__global__ __launch_bounds__(256) void out_kernel(
    const float* __restrict__ Wout, float* __restrict__ out)
{
    __shared__ float As[64 * 128];
    __shared__ float Wt[64 * 64];
    int tid = threadIdx.x;
    int n = blockIdx.x & 511, s0 = (blockIdx.x >> 9) * 128;

#pragma unroll
    for (int it = 0; it < 4; ++it) {
        int idx = it * 256 + tid;
        int c = idx & 63, kq = idx >> 6;
        float4 a = *(const float4*)(Wout + c * 64 + kq * 4);
        Wt[(kq * 4 + 0) * 64 + c] = a.x;
        Wt[(kq * 4 + 1) * 64 + c] = a.y;
        Wt[(kq * 4 + 2) * 64 + c] = a.z;
        Wt[(kq * 4 + 3) * 64 + c] = a.w;
    }

#pragma unroll
    for (int it = 0; it < 8; ++it) {
        int idx = it * 256 + tid;
        int c = idx >> 5, sq = idx & 31;
        *(float4*)(As + c * 128 + sq * 4) =
            *(const float4*)(g_o2 + ((size_t)c * 512 + n) * 512 + s0 + sq * 4);
    }
    __syncthreads();
#pragma unroll
    for (int it = 0; it < 8; ++it) {
        int idx = it * 256 + tid;
        int row = idx & 127, q = idx >> 7;
        float4 g4 = *(const float4*)(g_g + ((size_t)(s0 + row) * 512 + n) * CM + q * 4);
        As[(q * 4 + 0) * 128 + row] *= g4.x;
        As[(q * 4 + 1) * 128 + row] *= g4.y;
        As[(q * 4 + 2) * 128 + row] *= g4.z;
        As[(q * 4 + 3) * 128 + row] *= g4.w;
    }
    __syncthreads();

    int tx = tid & 15, ty = tid >> 4;
    float acc[8][4];
#pragma unroll
    for (int r = 0; r < 8; ++r)
#pragma unroll
        for (int c = 0; c < 4; ++c) acc[r][c] = 0.f;

#pragma unroll
    for (int k = 0; k < 64; ++k) {
        float4 a0 = *(const float4*)(As + k * 128 + ty * 4);
        float4 a1 = *(const float4*)(As + k * 128 + 64 + ty * 4);
        float4 w = *(const float4*)(Wt + k * 64 + tx * 4);
        float a[8] = {a0.x, a0.y, a0.z, a0.w, a1.x, a1.y, a1.z, a1.w};
        float wr[4] = {w.x, w.y, w.z, w.w};
#pragma unroll
        for (int r = 0; r < 8; ++r)
#pragma unroll
            for (int c = 0; c < 4; ++c)
                acc[r][c] = fmaf(a[r], wr[c], acc[r][c]);
    }
#pragma unroll
    for (int rh = 0; rh < 2; ++rh)
#pragma unroll
        for (int rr = 0; rr < 4; ++rr) {
            int orow = rh * 64 + ty * 4 + rr;
            float4 v4 = make_float4(acc[rh * 4 + rr][0], acc[rh * 4 + rr][1],
                                    acc[rh * 4 + rr][2], acc[rh * 4 + rr][3]);
            *(float4*)(out + ((size_t)(s0 + orow) * 512 + n) * CM + tx * 4) = v4;
        }
}

// ---------------------------------------------------------------------------
extern "C" void kernel_launch(void* const* d_in, const int* in_sizes, int n_in,
                              void* d_out, int out_size)
{
    const float* m    = (const float*)d_in[0];
    const float* z    = (const float*)d_in[1];
    const float* lnmw = (const float*)d_in[2];
    const float* lnmb = (const float*)d_in[3];
    const float* lnzw = (const float*)d_in[4];
    const float* lnzb = (const float*)d_in[5];
    const float* Wv   = (const float*)d_in[6];
    const float* Wb   = (const float*)d_in[7];
    const float* Wg   = (const float*)d_in[8];
    const float* Wout = (const float*)d_in[9];
    float* out = (float*)d_out;

    cudaFuncSetAttribute(pwa_mma_kernel,
                         cudaFuncAttributeMaxDynamicSharedMemorySize, PW_SMEMB);

    bias_ln_kernel<<<SQ * SQ / 8, 256>>>(z, lnzw, lnzb, Wb);
    softmax_kernel<<<SQ * NH, 256>>>();
    vg_kernel<<<SQ * NSEQ / 64, 256>>>(m, lnmw, lnmb, Wv, Wg);
    dim3 gD(32, 4, NH);
    pwa_mma_kernel<<<gD, 256, PW_SMEMB>>>();
    out_kernel<<<SQ * NSEQ / 128, 256>>>(Wout, out);
}

// round 4
// speedup vs baseline: 1.2482x; 1.0346x over previous
#include <cuda_runtime.h>
#include <cstdint>

#define SQ 512
#define NSEQ 512
#define CM 64
#define CZ 128
#define NH 8
#define EPS 1e-5f

// Scratch (device globals: allocation-free)
__device__ float g_w[(size_t)SQ * NH * SQ];        // raw logits->weights [i][h][j]
__device__ float g_wh[(size_t)SQ * NH * SQ];       // tf32-hi of weights
__device__ float g_wl[(size_t)SQ * NH * SQ];       // residual of weights
__device__ float g_vT[(size_t)CM * NSEQ * SQ];     // tf32-rounded v, [(c*512+n)*512 + j]
__device__ float g_g[(size_t)SQ * NSEQ * CM];      // gate [(s*512+n)*64 + c]
__device__ float g_o2[(size_t)CM * NSEQ * SQ];     // [(c*512+n)*512 + i]

__device__ __forceinline__ float warp_sum(float v) {
#pragma unroll
    for (int o = 16; o > 0; o >>= 1) v += __shfl_xor_sync(0xffffffffu, v, o);
    return v;
}
__device__ __forceinline__ float warp_max(float v) {
#pragma unroll
    for (int o = 16; o > 0; o >>= 1) v = fmaxf(v, __shfl_xor_sync(0xffffffffu, v, o));
    return v;
}
__device__ __forceinline__ uint32_t smem_u32(const void* p) {
    uint32_t a;
    asm("{ .reg .u64 t; cvta.to.shared.u64 t, %1; cvt.u32.u64 %0, t; }" : "=r"(a) : "l"(p));
    return a;
}
// round-to-nearest tf32 (keeps value in fp32 register, low 13 bits zero)
__device__ __forceinline__ float tf32rn(float x) {
    uint32_t r;
    asm("cvt.rna.tf32.f32 %0, %1;" : "=r"(r) : "f"(x));
    return __uint_as_float(r);
}
__device__ __forceinline__ void mma_tf32(float* d, const uint32_t* a,
                                         uint32_t b0, uint32_t b1) {
    asm volatile(
        "mma.sync.aligned.m16n8k8.row.col.f32.tf32.tf32.f32 "
        "{%0,%1,%2,%3}, {%4,%5,%6,%7}, {%8,%9}, {%0,%1,%2,%3};"
        : "+f"(d[0]), "+f"(d[1]), "+f"(d[2]), "+f"(d[3])
        : "r"(a[0]), "r"(a[1]), "r"(a[2]), "r"(a[3]), "r"(b0), "r"(b1));
}
#define CP_ASYNC16(dst, src) \
    asm volatile("cp.async.cg.shared.global [%0], [%1], 16;" :: "r"(dst), "l"(src))
#define CP_COMMIT() asm volatile("cp.async.commit_group;")
#define CP_WAIT(n)  asm volatile("cp.async.wait_group %0;" :: "n"(n))

// swizzled float index within a [rows][32-float] stage array
__device__ __forceinline__ int fidx32(int row, int k) {
    return row * 32 + ((((k >> 2) ^ (row & 7)) << 2) | (k & 3));
}

// ---------------------------------------------------------------------------
// Kernel 1: b[i,h,j] = LN(z[i,j,:]) . W_b[h,:]
// Block: 32 rows; phase A: warp-LN to smem; phase B: thread-per-(row,h) dot.
// ---------------------------------------------------------------------------
__global__ __launch_bounds__(256) void bias_ln_kernel(
    const float* __restrict__ z, const float* __restrict__ lnw,
    const float* __restrict__ lnb, const float* __restrict__ Wb)
{
    __shared__ float zn[32 * 132];
    __shared__ float wb[8 * 132];
    __shared__ float bs[256];
    int tid = threadIdx.x, warp = tid >> 5, lane = tid & 31;

    {   // Wb -> smem padded
        int h = tid >> 5;
        wb[h * 132 + lane * 4 + 0] = Wb[h * CZ + lane * 4 + 0];
        wb[h * 132 + lane * 4 + 1] = Wb[h * CZ + lane * 4 + 1];
        wb[h * 132 + lane * 4 + 2] = Wb[h * CZ + lane * 4 + 2];
        wb[h * 132 + lane * 4 + 3] = Wb[h * CZ + lane * 4 + 3];
    }

    size_t R0 = (size_t)blockIdx.x * 32;
#pragma unroll
    for (int rr = 0; rr < 4; ++rr) {
        int row = warp * 4 + rr;
        float4 x = *(const float4*)(z + (R0 + row) * CZ + lane * 4);
        float s = warp_sum(x.x + x.y + x.z + x.w);
        float mu = s * (1.0f / CZ);
        float d0 = x.x - mu, d1 = x.y - mu, d2 = x.z - mu, d3 = x.w - mu;
        float q = warp_sum(d0 * d0 + d1 * d1 + d2 * d2 + d3 * d3);
        float rs = rsqrtf(q * (1.0f / CZ) + EPS);
        int c = lane * 4;
        float4 nv;
        nv.x = d0 * rs * __ldg(lnw + c + 0) + __ldg(lnb + c + 0);
        nv.y = d1 * rs * __ldg(lnw + c + 1) + __ldg(lnb + c + 1);
        nv.z = d2 * rs * __ldg(lnw + c + 2) + __ldg(lnb + c + 2);
        nv.w = d3 * rs * __ldg(lnw + c + 3) + __ldg(lnb + c + 3);
        *(float4*)(zn + row * 132 + c) = nv;
    }
    __syncthreads();

    {   // per-thread dot: row = tid>>3, h = tid&7
        int row = tid >> 3, h = tid & 7;
        float acc = 0.f;
#pragma unroll
        for (int k = 0; k < 32; ++k) {
            float4 zv = *(const float4*)(zn + row * 132 + k * 4);
            float4 wv = *(const float4*)(wb + h * 132 + k * 4);
            acc = fmaf(zv.x, wv.x, acc);
            acc = fmaf(zv.y, wv.y, acc);
            acc = fmaf(zv.z, wv.z, acc);
            acc = fmaf(zv.w, wv.w, acc);
        }
        bs[h * 32 + row] = acc;
    }
    __syncthreads();
    int i = (int)(R0 >> 9), j0 = (int)(R0 & 511);
    g_w[(size_t)i * 4096 + warp * 512 + j0 + lane] = bs[warp * 32 + lane];
}

// ---------------------------------------------------------------------------
// Kernel 2: softmax over j; writes tf32 hi/lo split of the weights.
// ---------------------------------------------------------------------------
__global__ __launch_bounds__(256) void softmax_kernel()
{
    size_t base = (size_t)blockIdx.x * SQ;
    const float* row = g_w + base;
    __shared__ float sred[8];
    int tid = threadIdx.x, lane = tid & 31, warp = tid >> 5;

    float a = row[tid], b = row[tid + 256];
    float m = warp_max(fmaxf(a, b));
    if (lane == 0) sred[warp] = m;
    __syncthreads();
    float M = sred[0];
#pragma unroll
    for (int w = 1; w < 8; ++w) M = fmaxf(M, sred[w]);

    float e0 = __expf(a - M), e1 = __expf(b - M);
    float s = warp_sum(e0 + e1);
    __syncthreads();
    if (lane == 0) sred[warp] = s;
    __syncthreads();
    float tot = 0.f;
#pragma unroll
    for (int w = 0; w < 8; ++w) tot += sred[w];
    float inv = 1.0f / tot;
    float w0 = e0 * inv, w1 = e1 * inv;
    float h0 = tf32rn(w0), h1 = tf32rn(w1);
    g_wh[base + tid] = h0;        g_wl[base + tid] = w0 - h0;
    g_wh[base + tid + 256] = h1;  g_wl[base + tid + 256] = w1 - h1;
}

// ---------------------------------------------------------------------------
// Kernel 3: fused LN(m) -> mma -> vT (tf32-rounded) + gate.
// Block 256 thr: 128 rows (s for fixed n) x [v 64 | g 64], K=64.
// ---------------------------------------------------------------------------
#define VG_AH 0
#define VG_AL 8192
#define VG_BH 16384
#define VG_SMEMF 24576
#define VG_SMEMB (VG_SMEMF * 4)

__global__ __launch_bounds__(256, 1) void vg_kernel(
    const float* __restrict__ m, const float* __restrict__ lnw,
    const float* __restrict__ lnb, const float* __restrict__ Wv,
    const float* __restrict__ Wg)
{
    extern __shared__ float sm[];
    int tid = threadIdx.x, wid = tid >> 5, lane = tid & 31;
    int g = lane >> 2, tg = lane & 3;
    int n = blockIdx.x, s0 = blockIdx.y * 128;

    // ---- phase 1: LN(m) -> A hi/lo (swizzled), weights -> B hi (swizzled) ----
    {
        int row = tid >> 1, half = tid & 1;
        const float* src = m + ((size_t)(s0 + row) * 512 + n) * CM + half * 32;
        float v[32];
        float s = 0.f, q = 0.f;
#pragma unroll
        for (int qd = 0; qd < 8; ++qd) {
            float4 a = *(const float4*)(src + qd * 4);
            v[qd * 4 + 0] = a.x; v[qd * 4 + 1] = a.y;
            v[qd * 4 + 2] = a.z; v[qd * 4 + 3] = a.w;
            s += a.x + a.y + a.z + a.w;
            q += a.x * a.x + a.y * a.y + a.z * a.z + a.w * a.w;
        }
        s += __shfl_xor_sync(0xffffffffu, s, 1);
        q += __shfl_xor_sync(0xffffffffu, q, 1);
        float mu = s * (1.0f / CM);
        float var = q * (1.0f / CM) - mu * mu;
        float rs = rsqrtf(var + EPS);
#pragma unroll
        for (int qd = 0; qd < 8; ++qd) {
            int kq = half * 8 + qd;          // float4 index 0..15
            float4 hi, lo;
            float xs[4];
#pragma unroll
            for (int t = 0; t < 4; ++t) {
                int k = kq * 4 + t;
                xs[t] = (v[qd * 4 + t] - mu) * rs * __ldg(lnw + k) + __ldg(lnb + k);
            }
            hi = make_float4(tf32rn(xs[0]), tf32rn(xs[1]), tf32rn(xs[2]), tf32rn(xs[3]));
            lo = make_float4(xs[0] - hi.x, xs[1] - hi.y, xs[2] - hi.z, xs[3] - hi.w);
            int f4 = (kq >> 3) * 1024 + row * 8 + ((kq & 7) ^ (row & 7));
            *(float4*)(sm + VG_AH + f4 * 4) = hi;
            *(float4*)(sm + VG_AL + f4 * 4) = lo;
        }
        // weights: row = tid>>1 over combined [Wv;Wg] 128 rows
        const float* wsrc = (row < 64) ? (Wv + row * 64) : (Wg + (row - 64) * 64);
#pragma unroll
        for (int qd = 0; qd < 8; ++qd) {
            int kq = half * 8 + qd;
            float4 a = *(const float4*)(wsrc + kq * 4);
            float4 hi = make_float4(tf32rn(a.x), tf32rn(a.y), tf32rn(a.z), tf32rn(a.w));
            int f4 = (kq >> 3) * 1024 + row * 8 + ((kq & 7) ^ (row & 7));
            *(float4*)(sm + VG_BH + f4 * 4) = hi;
        }
    }
    __syncthreads();

    // ---- phase 2: mma ----
    int wi = (wid & 3) * 32, wn = (wid >> 2) * 64;
    float acc[2][8][4];
#pragma unroll
    for (int mt = 0; mt < 2; ++mt)
#pragma unroll
        for (int nt = 0; nt < 8; ++nt)
#pragma unroll
            for (int r = 0; r < 4; ++r) acc[mt][nt][r] = 0.f;

#pragma unroll
    for (int k8 = 0; k8 < 8; ++k8) {
        int kb = k8 * 8;
        int sec = (kb >> 5) * 4096;
        int kl = kb & 31;
        uint32_t ah[2][4], al[2][4];
#pragma unroll
        for (int mt = 0; mt < 2; ++mt) {
            int r0 = wi + mt * 16 + g;
            ah[mt][0] = __float_as_uint(sm[VG_AH + sec + fidx32(r0, kl + tg)]);
            ah[mt][1] = __float_as_uint(sm[VG_AH + sec + fidx32(r0 + 8, kl + tg)]);
            ah[mt][2] = __float_as_uint(sm[VG_AH + sec + fidx32(r0, kl + 4 + tg)]);
            ah[mt][3] = __float_as_uint(sm[VG_AH + sec + fidx32(r0 + 8, kl + 4 + tg)]);
            al[mt][0] = __float_as_uint(sm[VG_AL + sec + fidx32(r0, kl + tg)]);
            al[mt][1] = __float_as_uint(sm[VG_AL + sec + fidx32(r0 + 8, kl + tg)]);
            al[mt][2] = __float_as_uint(sm[VG_AL + sec + fidx32(r0, kl + 4 + tg)]);
            al[mt][3] = __float_as_uint(sm[VG_AL + sec + fidx32(r0 + 8, kl + 4 + tg)]);
        }
#pragma unroll
        for (int nt = 0; nt < 8; ++nt) {
            int n0 = wn + nt * 8 + g;
            uint32_t b0 = __float_as_uint(sm[VG_BH + sec + fidx32(n0, kl + tg)]);
            uint32_t b1 = __float_as_uint(sm[VG_BH + sec + fidx32(n0, kl + 4 + tg)]);
#pragma unroll
            for (int mt = 0; mt < 2; ++mt) {
                mma_tf32(acc[mt][nt], ah[mt], b0, b1);
                mma_tf32(acc[mt][nt], al[mt], b0, b1);
            }
        }
    }
    __syncthreads();

    // ---- phase 3: epilogue (stage in smem, coalesced stores) ----
    float* Cs = sm;              // v: [c 64][132]
    float* Cg = sm + 8448;       // g: [row 128][68]
#pragma unroll
    for (int mt = 0; mt < 2; ++mt) {
        int r = wi + mt * 16 + g;
#pragma unroll
        for (int nt = 0; nt < 8; ++nt) {
            int col = wn + nt * 8 + 2 * tg;
            if (wid < 4) {       // v half
                Cs[col * 132 + r]            = acc[mt][nt][0];
                Cs[(col + 1) * 132 + r]      = acc[mt][nt][1];
                Cs[col * 132 + r + 8]        = acc[mt][nt][2];
                Cs[(col + 1) * 132 + r + 8]  = acc[mt][nt][3];
            } else {             // g half (cols 64..127)
                int c = col - 64;
                Cg[r * 68 + c]           = 1.0f / (1.0f + __expf(-acc[mt][nt][0]));
                Cg[r * 68 + c + 1]       = 1.0f / (1.0f + __expf(-acc[mt][nt][1]));
                Cg[(r + 8) * 68 + c]     = 1.0f / (1.0f + __expf(-acc[mt][nt][2]));
                Cg[(r + 8) * 68 + c + 1] = 1.0f / (1.0f + __expf(-acc[mt][nt][3]));
            }
        }
    }
    __syncthreads();
#pragma unroll
    for (int it = 0; it < 8; ++it) {     // vT stores (tf32-rounded)
        int idx = it * 256 + tid;
        int c = idx >> 5, q = idx & 31;
        float4 v4 = *(const float4*)(Cs + c * 132 + q * 4);
        v4 = make_float4(tf32rn(v4.x), tf32rn(v4.y), tf32rn(v4.z), tf32rn(v4.w));
        *(float4*)(g_vT + ((size_t)c * 512 + n) * 512 + s0 + q * 4) = v4;
    }
#pragma unroll
    for (int it = 0; it < 8; ++it) {     // gate stores
        int idx = it * 256 + tid;
        int r = idx >> 4, q = idx & 15;
        float4 g4 = *(const float4*)(Cg + r * 68 + q * 4);
        *(float4*)(g_g + ((size_t)(s0 + r) * 512 + n) * CM + q * 4) = g4;
    }
}

// ---------------------------------------------------------------------------
// Kernel 4: pwa 2-term TF32 mma GEMM, cp.async pipelined.
// Block 512 thr: M=256(i) x N=128(nd), K=512, kc=32, 2 stages.
// ---------------------------------------------------------------------------
#define PW_STGB 81920                      // bytes per stage
#define PW_STGF 20480                      // floats per stage
#define PW_SMEMB (2 * PW_STGB)

__device__ __forceinline__ void pw_ldstage(uint32_t sb, int tid,
                                           const float* Ah_g, const float* Al_g,
                                           const float* Bh_g, int k0)
{
#pragma unroll
    for (int it = 0; it < 4; ++it) {       // A: 256 rows x 32 k, hi+lo
        int id = it * 512 + tid;
        int row = id >> 3, q = id & 7;
        uint32_t d = sb + (uint32_t)((row * 8 + (q ^ (row & 7))) * 16);
        size_t off = (size_t)row * 4096 + k0 + q * 4;
        CP_ASYNC16(d, Ah_g + off);
        CP_ASYNC16(d + 32768, Al_g + off);
    }
#pragma unroll
    for (int it = 0; it < 2; ++it) {       // B: 128 rows x 32 k, hi
        int id = it * 512 + tid;
        int row = id >> 3, q = id & 7;
        uint32_t d = sb + 65536 + (uint32_t)((row * 8 + (q ^ (row & 7))) * 16);
        CP_ASYNC16(d, Bh_g + (size_t)row * 512 + k0 + q * 4);
    }
}

__global__ __launch_bounds__(512, 1) void pwa_mma_kernel()
{
    extern __shared__ float sm[];
    uint32_t sbase = smem_u32(sm);
    int tid = threadIdx.x, wid = tid >> 5, lane = tid & 31;
    int g = lane >> 2, tg = lane & 3;
    int h = blockIdx.z;
    int i0 = blockIdx.y * 256;
    int nd0 = blockIdx.x * 128;
    const float* Ah_g = g_wh + (size_t)i0 * 4096 + h * 512;
    const float* Al_g = g_wl + (size_t)i0 * 4096 + h * 512;
    const float* Bh_g = g_vT + ((size_t)h * 4096 + nd0) * 512;

    int wi = (wid & 3) * 64, wn = (wid >> 2) * 32;

    float acc[4][4][4];
#pragma unroll
    for (int mt = 0; mt < 4; ++mt)
#pragma unroll
        for (int nt = 0; nt < 4; ++nt)
#pragma unroll
            for (int r = 0; r < 4; ++r) acc[mt][nt][r] = 0.f;

    pw_ldstage(sbase, tid, Ah_g, Al_g, Bh_g, 0);
    CP_COMMIT();

    for (int c = 0; c < 16; ++c) {
        int buf = c & 1;
        if (c < 15) {
            pw_ldstage(sbase + (buf ^ 1) * PW_STGB, tid, Ah_g, Al_g, Bh_g, (c + 1) * 32);
            CP_COMMIT();
            CP_WAIT(1);
        } else {
            CP_WAIT(0);
        }
        __syncthreads();

        const float* Ah = sm + buf * PW_STGF;
        const float* Al = Ah + 8192;
        const float* Bh = Ah + 16384;
#pragma unroll
        for (int kk = 0; kk < 4; ++kk) {
            int kb = kk * 8;
            uint32_t ah[4][4], al[4][4];
#pragma unroll
            for (int mt = 0; mt < 4; ++mt) {
                int r0 = wi + mt * 16 + g;
                ah[mt][0] = __float_as_uint(Ah[fidx32(r0, kb + tg)]);
                ah[mt][1] = __float_as_uint(Ah[fidx32(r0 + 8, kb + tg)]);
                ah[mt][2] = __float_as_uint(Ah[fidx32(r0, kb + 4 + tg)]);
                ah[mt][3] = __float_as_uint(Ah[fidx32(r0 + 8, kb + 4 + tg)]);
                al[mt][0] = __float_as_uint(Al[fidx32(r0, kb + tg)]);
                al[mt][1] = __float_as_uint(Al[fidx32(r0 + 8, kb + tg)]);
                al[mt][2] = __float_as_uint(Al[fidx32(r0, kb + 4 + tg)]);
                al[mt][3] = __float_as_uint(Al[fidx32(r0 + 8, kb + 4 + tg)]);
            }
#pragma unroll
            for (int nt = 0; nt < 4; ++nt) {
                int n0 = wn + nt * 8 + g;
                uint32_t b0 = __float_as_uint(Bh[fidx32(n0, kb + tg)]);
                uint32_t b1 = __float_as_uint(Bh[fidx32(n0, kb + 4 + tg)]);
#pragma unroll
                for (int mt = 0; mt < 4; ++mt) {
                    mma_tf32(acc[mt][nt], ah[mt], b0, b1);
                    mma_tf32(acc[mt][nt], al[mt], b0, b1);
                }
            }
        }
        __syncthreads();
    }

    // ---- epilogue: stage C [col 128][260 rows], coalesced stores ----
    float* Cs = sm;
#pragma unroll
    for (int mt = 0; mt < 4; ++mt) {
        int r = wi + mt * 16 + g;
#pragma unroll
        for (int nt = 0; nt < 4; ++nt) {
            int col = wn + nt * 8 + 2 * tg;
            Cs[col * 260 + r]            = acc[mt][nt][0];
            Cs[(col + 1) * 260 + r]      = acc[mt][nt][1];
            Cs[col * 260 + r + 8]        = acc[mt][nt][2];
            Cs[(col + 1) * 260 + r + 8]  = acc[mt][nt][3];
        }
    }
    __syncthreads();
    size_t obase = ((size_t)h * 4096 + nd0) * 512 + i0;
#pragma unroll
    for (int it = 0; it < 16; ++it) {
        int idx = it * 512 + tid;
        int col = idx >> 6, rq = idx & 63;
        *(float4*)(g_o2 + obase + (size_t)col * 512 + rq * 4) =
            *(const float4*)(Cs + col * 260 + rq * 4);
    }
}

// ---------------------------------------------------------------------------
// Kernel 5: out = (g .* o) @ Wout^T  (SIMT, unchanged)
// ---------------------------------------------------------------------------
__global__ __launch_bounds__(256) void out_kernel(
    const float* __restrict__ Wout, float* __restrict__ out)
{
    __shared__ float As[64 * 128];
    __shared__ float Wt[64 * 64];
    int tid = threadIdx.x;
    int n = blockIdx.x & 511, s0 = (blockIdx.x >> 9) * 128;

#pragma unroll
    for (int it = 0; it < 4; ++it) {
        int idx = it * 256 + tid;
        int c = idx & 63, kq = idx >> 6;
        float4 a = *(const float4*)(Wout + c * 64 + kq * 4);
        Wt[(kq * 4 + 0) * 64 + c] = a.x;
        Wt[(kq * 4 + 1) * 64 + c] = a.y;
        Wt[(kq * 4 + 2) * 64 + c] = a.z;
        Wt[(kq * 4 + 3) * 64 + c] = a.w;
    }

#pragma unroll
    for (int it = 0; it < 8; ++it) {
        int idx = it * 256 + tid;
        int c = idx >> 5, sq = idx & 31;
        *(float4*)(As + c * 128 + sq * 4) =
            *(const float4*)(g_o2 + ((size_t)c * 512 + n) * 512 + s0 + sq * 4);
    }
    __syncthreads();
#pragma unroll
    for (int it = 0; it < 8; ++it) {
        int idx = it * 256 + tid;
        int row = idx & 127, q = idx >> 7;
        float4 g4 = *(const float4*)(g_g + ((size_t)(s0 + row) * 512 + n) * CM + q * 4);
        As[(q * 4 + 0) * 128 + row] *= g4.x;
        As[(q * 4 + 1) * 128 + row] *= g4.y;
        As[(q * 4 + 2) * 128 + row] *= g4.z;
        As[(q * 4 + 3) * 128 + row] *= g4.w;
    }
    __syncthreads();

    int tx = tid & 15, ty = tid >> 4;
    float acc[8][4];
#pragma unroll
    for (int r = 0; r < 8; ++r)
#pragma unroll
        for (int c = 0; c < 4; ++c) acc[r][c] = 0.f;

#pragma unroll
    for (int k = 0; k < 64; ++k) {
        float4 a0 = *(const float4*)(As + k * 128 + ty * 4);
        float4 a1 = *(const float4*)(As + k * 128 + 64 + ty * 4);
        float4 w = *(const float4*)(Wt + k * 64 + tx * 4);
        float a[8] = {a0.x, a0.y, a0.z, a0.w, a1.x, a1.y, a1.z, a1.w};
        float wr[4] = {w.x, w.y, w.z, w.w};
#pragma unroll
        for (int r = 0; r < 8; ++r)
#pragma unroll
            for (int c = 0; c < 4; ++c)
                acc[r][c] = fmaf(a[r], wr[c], acc[r][c]);
    }
#pragma unroll
    for (int rh = 0; rh < 2; ++rh)
#pragma unroll
        for (int rr = 0; rr < 4; ++rr) {
            int orow = rh * 64 + ty * 4 + rr;
            float4 v4 = make_float4(acc[rh * 4 + rr][0], acc[rh * 4 + rr][1],
                                    acc[rh * 4 + rr][2], acc[rh * 4 + rr][3]);
            *(float4*)(out + ((size_t)(s0 + orow) * 512 + n) * CM + tx * 4) = v4;
        }
}

// ---------------------------------------------------------------------------
extern "C" void kernel_launch(void* const* d_in, const int* in_sizes, int n_in,
                              void* d_out, int out_size)
{
    const float* m    = (const float*)d_in[0];
    const float* z    = (const float*)d_in[1];
    const float* lnmw = (const float*)d_in[2];
    const float* lnmb = (const float*)d_in[3];
    const float* lnzw = (const float*)d_in[4];
    const float* lnzb = (const float*)d_in[5];
    const float* Wv   = (const float*)d_in[6];
    const float* Wb   = (const float*)d_in[7];
    const float* Wg   = (const float*)d_in[8];
    const float* Wout = (const float*)d_in[9];
    float* out = (float*)d_out;

    cudaFuncSetAttribute(pwa_mma_kernel,
                         cudaFuncAttributeMaxDynamicSharedMemorySize, PW_SMEMB);
    cudaFuncSetAttribute(vg_kernel,
                         cudaFuncAttributeMaxDynamicSharedMemorySize, VG_SMEMB);

    bias_ln_kernel<<<SQ * SQ / 32, 256>>>(z, lnzw, lnzb, Wb);
    softmax_kernel<<<SQ * NH, 256>>>();
    vg_kernel<<<dim3(512, 4), 256, VG_SMEMB>>>(m, lnmw, lnmb, Wv, Wg);
    dim3 gD(32, 2, NH);
    pwa_mma_kernel<<<gD, 512, PW_SMEMB>>>();
    out_kernel<<<SQ * NSEQ / 128, 256>>>(Wout, out);
}

// round 6
// speedup vs baseline: 1.3610x; 1.0904x over previous
#include <cuda_runtime.h>
#include <cstdint>

#define SQ 512
#define NSEQ 512
#define CM 64
#define CZ 128
#define NH 8
#define EPS 1e-5f

// Scratch (device globals: allocation-free)
__device__ float g_w[(size_t)SQ * NH * SQ];        // raw logits [i][h][j]
__device__ float g_whf[(size_t)SQ * NH * SQ];      // w hi, A-frag layout [I][h][jg][lane][4]
__device__ float g_wlf[(size_t)SQ * NH * SQ];      // w lo, same layout
__device__ float g_vTf[(size_t)CM * NSEQ * SQ];    // v, B-frag layout [h][ndg][jg][lane][2]
__device__ float g_g[(size_t)SQ * NSEQ * CM];      // gate [(s*512+n)*64 + c]
__device__ float g_o2[(size_t)CM * NSEQ * SQ];     // [(c*512+n)*512 + i]

__device__ __forceinline__ float warp_sum(float v) {
#pragma unroll
    for (int o = 16; o > 0; o >>= 1) v += __shfl_xor_sync(0xffffffffu, v, o);
    return v;
}
__device__ __forceinline__ float warp_max(float v) {
#pragma unroll
    for (int o = 16; o > 0; o >>= 1) v = fmaxf(v, __shfl_xor_sync(0xffffffffu, v, o));
    return v;
}
__device__ __forceinline__ uint32_t smem_u32(const void* p) {
    uint32_t a;
    asm("{ .reg .u64 t; cvta.to.shared.u64 t, %1; cvt.u32.u64 %0, t; }" : "=r"(a) : "l"(p));
    return a;
}
__device__ __forceinline__ float tf32rn(float x) {
    uint32_t r;
    asm("cvt.rna.tf32.f32 %0, %1;" : "=r"(r) : "f"(x));
    return __uint_as_float(r);
}
__device__ __forceinline__ void mma_tf32(float* d, const uint32_t* a,
                                         uint32_t b0, uint32_t b1) {
    asm volatile(
        "mma.sync.aligned.m16n8k8.row.col.f32.tf32.tf32.f32 "
        "{%0,%1,%2,%3}, {%4,%5,%6,%7}, {%8,%9}, {%0,%1,%2,%3};"
        : "+f"(d[0]), "+f"(d[1]), "+f"(d[2]), "+f"(d[3])
        : "r"(a[0]), "r"(a[1]), "r"(a[2]), "r"(a[3]), "r"(b0), "r"(b1));
}
#define CP_ASYNC16(dst, src) \
    asm volatile("cp.async.cg.shared.global [%0], [%1], 16;" :: "r"(dst), "l"(src))
#define CP_COMMIT() asm volatile("cp.async.commit_group;")
#define CP_WAIT(n)  asm volatile("cp.async.wait_group %0;" :: "n"(n))

// swizzled float index (used by vg phase-2 only)
__device__ __forceinline__ int fidx32(int row, int k) {
    return row * 32 + ((((k >> 2) ^ (row & 7)) << 2) | (k & 3));
}

// ---------------------------------------------------------------------------
// Kernel 1: b[i,h,j] = LN(z[i,j,:]) . W_b[h,:]  -> g_w (row-major logits)
// ---------------------------------------------------------------------------
__global__ __launch_bounds__(256) void bias_ln_kernel(
    const float* __restrict__ z, const float* __restrict__ lnw,
    const float* __restrict__ lnb, const float* __restrict__ Wb)
{
    __shared__ float zn[32 * 132];
    __shared__ float wb[8 * 132];
    __shared__ float bs[256];
    int tid = threadIdx.x, warp = tid >> 5, lane = tid & 31;

    {
        int h = tid >> 5;
        wb[h * 132 + lane * 4 + 0] = Wb[h * CZ + lane * 4 + 0];
        wb[h * 132 + lane * 4 + 1] = Wb[h * CZ + lane * 4 + 1];
        wb[h * 132 + lane * 4 + 2] = Wb[h * CZ + lane * 4 + 2];
        wb[h * 132 + lane * 4 + 3] = Wb[h * CZ + lane * 4 + 3];
    }

    size_t R0 = (size_t)blockIdx.x * 32;
#pragma unroll
    for (int rr = 0; rr < 4; ++rr) {
        int row = warp * 4 + rr;
        float4 x = *(const float4*)(z + (R0 + row) * CZ + lane * 4);
        float s = warp_sum(x.x + x.y + x.z + x.w);
        float mu = s * (1.0f / CZ);
        float d0 = x.x - mu, d1 = x.y - mu, d2 = x.z - mu, d3 = x.w - mu;
        float q = warp_sum(d0 * d0 + d1 * d1 + d2 * d2 + d3 * d3);
        float rs = rsqrtf(q * (1.0f / CZ) + EPS);
        int c = lane * 4;
        float4 nv;
        nv.x = d0 * rs * __ldg(lnw + c + 0) + __ldg(lnb + c + 0);
        nv.y = d1 * rs * __ldg(lnw + c + 1) + __ldg(lnb + c + 1);
        nv.z = d2 * rs * __ldg(lnw + c + 2) + __ldg(lnb + c + 2);
        nv.w = d3 * rs * __ldg(lnw + c + 3) + __ldg(lnb + c + 3);
        *(float4*)(zn + row * 132 + c) = nv;
    }
    __syncthreads();

    {
        int row = tid >> 3, h = tid & 7;
        float acc = 0.f;
#pragma unroll
        for (int k = 0; k < 32; ++k) {
            float4 zv = *(const float4*)(zn + row * 132 + k * 4);
            float4 wv = *(const float4*)(wb + h * 132 + k * 4);
            acc = fmaf(zv.x, wv.x, acc);
            acc = fmaf(zv.y, wv.y, acc);
            acc = fmaf(zv.z, wv.z, acc);
            acc = fmaf(zv.w, wv.w, acc);
        }
        bs[h * 32 + row] = acc;
    }
    __syncthreads();
    int i = (int)(R0 >> 9), j0 = (int)(R0 & 511);
    g_w[(size_t)i * 4096 + warp * 512 + j0 + lane] = bs[warp * 32 + lane];
}

// ---------------------------------------------------------------------------
// Kernel 2: softmax over j; emits A-fragment-layout hi/lo slabs.
// ---------------------------------------------------------------------------
#define SMX_SMEMB (2 * 8704 * 4)
__global__ __launch_bounds__(256, 1) void softmax_kernel()
{
    extern __shared__ float sx[];
    float* smh = sx;            // [j*17 + i_loc]
    float* sml = sx + 8704;
    int tid = threadIdx.x;
    int row = tid >> 4, l = tid & 15;
    int I = blockIdx.x >> 3, h = blockIdx.x & 7;
    const float* src = g_w + ((size_t)(I * 16 + row)) * 4096 + h * 512;

    float w[32];
    float mx = -1e30f;
#pragma unroll
    for (int jj = 0; jj < 32; ++jj) {
        w[jj] = src[jj * 16 + l];
        mx = fmaxf(mx, w[jj]);
    }
#pragma unroll
    for (int o = 8; o > 0; o >>= 1) mx = fmaxf(mx, __shfl_xor_sync(0xffffffffu, mx, o));
    float sum = 0.f;
#pragma unroll
    for (int jj = 0; jj < 32; ++jj) {
        w[jj] = __expf(w[jj] - mx);
        sum += w[jj];
    }
#pragma unroll
    for (int o = 8; o > 0; o >>= 1) sum += __shfl_xor_sync(0xffffffffu, sum, o);
    float inv = 1.0f / sum;
#pragma unroll
    for (int jj = 0; jj < 32; ++jj) {
        int j = jj * 16 + l;
        float wv = w[jj] * inv;
        float hv = tf32rn(wv);
        smh[j * 17 + row] = hv;
        sml[j * 17 + row] = wv - hv;
    }
    __syncthreads();

    float* dh = g_whf + (size_t)(I * 8 + h) * 8192;
    float* dl = g_wlf + (size_t)(I * 8 + h) * 8192;
#pragma unroll
    for (int it = 0; it < 8; ++it) {
        int u = it * 256 + tid;
        int jg = u >> 5, lane = u & 31;
        float4 vh, vl;
#pragma unroll
        for (int idx = 0; idx < 4; ++idx) {
            int il = (lane >> 2) + (idx & 1) * 8;
            int j = jg * 8 + ((idx >> 1) & 1) * 4 + (lane & 3);
            (&vh.x)[idx] = smh[j * 17 + il];
            (&vl.x)[idx] = sml[j * 17 + il];
        }
        *(float4*)(dh + u * 4) = vh;
        *(float4*)(dl + u * 4) = vl;
    }
}

// ---------------------------------------------------------------------------
// Kernel 3: fused LN(m) -> mma -> vT (B-frag layout) + gate.
// ---------------------------------------------------------------------------
#define VG_AH 0
#define VG_AL 8192
#define VG_BH 16384
#define VG_SMEMF 24576
#define VG_SMEMB (VG_SMEMF * 4)

__global__ __launch_bounds__(256, 1) void vg_kernel(
    const float* __restrict__ m, const float* __restrict__ lnw,
    const float* __restrict__ lnb, const float* __restrict__ Wv,
    const float* __restrict__ Wg)
{
    extern __shared__ float sm[];
    int tid = threadIdx.x, wid = tid >> 5, lane = tid & 31;
    int g = lane >> 2, tg = lane & 3;
    int n = blockIdx.x, s0 = blockIdx.y * 128;

    {   // phase 1: LN + split to swizzled smem
        int row = tid >> 1, half = tid & 1;
        const float* src = m + ((size_t)(s0 + row) * 512 + n) * CM + half * 32;
        float v[32];
        float s = 0.f, q = 0.f;
#pragma unroll
        for (int qd = 0; qd < 8; ++qd) {
            float4 a = *(const float4*)(src + qd * 4);
            v[qd * 4 + 0] = a.x; v[qd * 4 + 1] = a.y;
            v[qd * 4 + 2] = a.z; v[qd * 4 + 3] = a.w;
            s += a.x + a.y + a.z + a.w;
            q += a.x * a.x + a.y * a.y + a.z * a.z + a.w * a.w;
        }
        s += __shfl_xor_sync(0xffffffffu, s, 1);
        q += __shfl_xor_sync(0xffffffffu, q, 1);
        float mu = s * (1.0f / CM);
        float var = q * (1.0f / CM) - mu * mu;
        float rs = rsqrtf(var + EPS);
#pragma unroll
        for (int qd = 0; qd < 8; ++qd) {
            int kq = half * 8 + qd;
            float xs[4];
#pragma unroll
            for (int t = 0; t < 4; ++t) {
                int k = kq * 4 + t;
                xs[t] = (v[qd * 4 + t] - mu) * rs * __ldg(lnw + k) + __ldg(lnb + k);
            }
            float4 hi = make_float4(tf32rn(xs[0]), tf32rn(xs[1]), tf32rn(xs[2]), tf32rn(xs[3]));
            float4 lo = make_float4(xs[0] - hi.x, xs[1] - hi.y, xs[2] - hi.z, xs[3] - hi.w);
            int f4 = (kq >> 3) * 1024 + row * 8 + ((kq & 7) ^ (row & 7));
            *(float4*)(sm + VG_AH + f4 * 4) = hi;
            *(float4*)(sm + VG_AL + f4 * 4) = lo;
        }
        const float* wsrc = (row < 64) ? (Wv + row * 64) : (Wg + (row - 64) * 64);
#pragma unroll
        for (int qd = 0; qd < 8; ++qd) {
            int kq = half * 8 + qd;
            float4 a = *(const float4*)(wsrc + kq * 4);
            float4 hi = make_float4(tf32rn(a.x), tf32rn(a.y), tf32rn(a.z), tf32rn(a.w));
            int f4 = (kq >> 3) * 1024 + row * 8 + ((kq & 7) ^ (row & 7));
            *(float4*)(sm + VG_BH + f4 * 4) = hi;
        }
    }
    __syncthreads();

    // phase 2: mma
    int wi = (wid & 3) * 32, wn = (wid >> 2) * 64;
    float acc[2][8][4];
#pragma unroll
    for (int mt = 0; mt < 2; ++mt)
#pragma unroll
        for (int nt = 0; nt < 8; ++nt)
#pragma unroll
            for (int r = 0; r < 4; ++r) acc[mt][nt][r] = 0.f;

#pragma unroll
    for (int k8 = 0; k8 < 8; ++k8) {
        int kb = k8 * 8;
        int sec = (kb >> 5) * 4096;
        int kl = kb & 31;
        uint32_t ah[2][4], al[2][4];
#pragma unroll
        for (int mt = 0; mt < 2; ++mt) {
            int r0 = wi + mt * 16 + g;
            ah[mt][0] = __float_as_uint(sm[VG_AH + sec + fidx32(r0, kl + tg)]);
            ah[mt][1] = __float_as_uint(sm[VG_AH + sec + fidx32(r0 + 8, kl + tg)]);
            ah[mt][2] = __float_as_uint(sm[VG_AH + sec + fidx32(r0, kl + 4 + tg)]);
            ah[mt][3] = __float_as_uint(sm[VG_AH + sec + fidx32(r0 + 8, kl + 4 + tg)]);
            al[mt][0] = __float_as_uint(sm[VG_AL + sec + fidx32(r0, kl + tg)]);
            al[mt][1] = __float_as_uint(sm[VG_AL + sec + fidx32(r0 + 8, kl + tg)]);
            al[mt][2] = __float_as_uint(sm[VG_AL + sec + fidx32(r0, kl + 4 + tg)]);
            al[mt][3] = __float_as_uint(sm[VG_AL + sec + fidx32(r0 + 8, kl + 4 + tg)]);
        }
#pragma unroll
        for (int nt = 0; nt < 8; ++nt) {
            int n0 = wn + nt * 8 + g;
            uint32_t b0 = __float_as_uint(sm[VG_BH + sec + fidx32(n0, kl + tg)]);
            uint32_t b1 = __float_as_uint(sm[VG_BH + sec + fidx32(n0, kl + 4 + tg)]);
#pragma unroll
            for (int mt = 0; mt < 2; ++mt) {
                mma_tf32(acc[mt][nt], ah[mt], b0, b1);
                mma_tf32(acc[mt][nt], al[mt], b0, b1);
            }
        }
    }
    __syncthreads();

    // phase 3: epilogue
    float* Cs = sm;              // v: [c 64][132]
    float* Cg = sm + 8448;       // g: [row 128][68]
#pragma unroll
    for (int mt = 0; mt < 2; ++mt) {
        int r = wi + mt * 16 + g;
#pragma unroll
        for (int nt = 0; nt < 8; ++nt) {
            int col = wn + nt * 8 + 2 * tg;
            if (wid < 4) {
                Cs[col * 132 + r]            = acc[mt][nt][0];
                Cs[(col + 1) * 132 + r]      = acc[mt][nt][1];
                Cs[col * 132 + r + 8]        = acc[mt][nt][2];
                Cs[(col + 1) * 132 + r + 8]  = acc[mt][nt][3];
            } else {
                int c = col - 64;
                Cg[r * 68 + c]           = 1.0f / (1.0f + __expf(-acc[mt][nt][0]));
                Cg[r * 68 + c + 1]       = 1.0f / (1.0f + __expf(-acc[mt][nt][1]));
                Cg[(r + 8) * 68 + c]     = 1.0f / (1.0f + __expf(-acc[mt][nt][2]));
                Cg[(r + 8) * 68 + c + 1] = 1.0f / (1.0f + __expf(-acc[mt][nt][3]));
            }
        }
    }
    __syncthreads();
    // vT -> B-frag layout: [h][ndg][jg][lane=gpos*4+tg][2]
    // nd = d*512 + n; ndg = d*64 + (n>>3); gpos = n&7.  (FIXED in R6)
#pragma unroll
    for (int it = 0; it < 16; ++it) {
        int u = it * 256 + tid;
        int c = u >> 6, rem = u & 63;
        int jgl = rem >> 2, j3 = rem & 3;
        int sl = jgl * 8 + j3;
        float v0 = tf32rn(Cs[c * 132 + sl]);
        float v1 = tf32rn(Cs[c * 132 + sl + 4]);
        int d = c & 7, hh = c >> 3;
        int ndg = d * 64 + (n >> 3);
        int gpos = n & 7;
        size_t off = (((size_t)hh * 512 + ndg) * 64 + (size_t)((s0 >> 3) + jgl)) * 64
                   + (gpos * 4 + j3) * 2;
        *(float2*)(g_vTf + off) = make_float2(v0, v1);
    }
#pragma unroll
    for (int it = 0; it < 8; ++it) {
        int idx = it * 256 + tid;
        int r = idx >> 4, q = idx & 15;
        float4 g4 = *(const float4*)(Cg + r * 68 + q * 4);
        *(float4*)(g_g + ((size_t)(s0 + r) * 512 + n) * CM + q * 4) = g4;
    }
}

// ---------------------------------------------------------------------------
// Kernel 4: pwa 2-term TF32 mma GEMM, fragment-native smem, cp.async.
// ---------------------------------------------------------------------------
#define PW_STGB 81920
#define PW_STGF 20480
#define PW_SMEMB (2 * PW_STGB)

__device__ __forceinline__ void pw_ldstage(uint32_t sb, int tid,
                                           const float* Ah_g, const float* Al_g,
                                           const float* Bg, int chunk)
{
    int jg0 = chunk * 4;
#pragma unroll
    for (int it = 0; it < 4; ++it) {
        int t = it * 512 + tid;
        int Igl = t >> 7, rem = t & 127;
        int jgl = rem >> 5, part = rem & 31;
        size_t src = (size_t)Igl * 65536 + (jg0 + jgl) * 128 + part * 4;
        uint32_t d = sb + (uint32_t)t * 16;
        CP_ASYNC16(d, Ah_g + src);
        CP_ASYNC16(d + 32768, Al_g + src);
    }
#pragma unroll
    for (int it = 0; it < 2; ++it) {
        int t = it * 512 + tid;
        int ndgl = t >> 6, rem = t & 63;
        int jgl = rem >> 4, part = rem & 15;
        size_t src = (size_t)ndgl * 4096 + (jg0 + jgl) * 64 + part * 4;
        CP_ASYNC16(sb + 65536 + (uint32_t)t * 16, Bg + src);
    }
}

__global__ __launch_bounds__(512, 1) void pwa_mma_kernel()
{
    extern __shared__ float sm[];
    uint32_t sbase = smem_u32(sm);
    int tid = threadIdx.x, wid = tid >> 5, lane = tid & 31;
    int g = lane >> 2, tg = lane & 3;
    int h = blockIdx.z;
    int i0 = blockIdx.y * 256;
    int nd0 = blockIdx.x * 128;
    const float* Ah_g = g_whf + (size_t)((i0 >> 4) * 8 + h) * 8192;
    const float* Al_g = g_wlf + (size_t)((i0 >> 4) * 8 + h) * 8192;
    const float* Bg   = g_vTf + (size_t)(h * 512 + (nd0 >> 3)) * 4096;

    int iw = (wid & 3) * 4;
    int nw = (wid >> 2) * 4;
    int wi = (wid & 3) * 64, wn = (wid >> 2) * 32;

    float acc[4][4][4];
#pragma unroll
    for (int mt = 0; mt < 4; ++mt)
#pragma unroll
        for (int nt = 0; nt < 4; ++nt)
#pragma unroll
            for (int r = 0; r < 4; ++r) acc[mt][nt][r] = 0.f;

    pw_ldstage(sbase, tid, Ah_g, Al_g, Bg, 0);
    CP_COMMIT();

    for (int c = 0; c < 16; ++c) {
        int buf = c & 1;
        if (c < 15) {
            pw_ldstage(sbase + (buf ^ 1) * PW_STGB, tid, Ah_g, Al_g, Bg, c + 1);
            CP_COMMIT();
            CP_WAIT(1);
        } else {
            CP_WAIT(0);
        }
        __syncthreads();

        const float* Ah = sm + buf * PW_STGF;
        const float* Al = Ah + 8192;
        const float* Bh = Ah + 16384;
#pragma unroll
        for (int kk = 0; kk < 4; ++kk) {
            float4 ahv[4], alv[4];
#pragma unroll
            for (int mt = 0; mt < 4; ++mt) {
                int blk = ((iw + mt) * 4 + kk) * 128 + lane * 4;
                ahv[mt] = *(const float4*)(Ah + blk);
                alv[mt] = *(const float4*)(Al + blk);
            }
#pragma unroll
            for (int nt = 0; nt < 4; ++nt) {
                float2 bv = *(const float2*)(Bh + ((nw + nt) * 4 + kk) * 64 + lane * 2);
                uint32_t b0 = __float_as_uint(bv.x);
                uint32_t b1 = __float_as_uint(bv.y);
#pragma unroll
                for (int mt = 0; mt < 4; ++mt) {
                    mma_tf32(acc[mt][nt], (const uint32_t*)&ahv[mt], b0, b1);
                    mma_tf32(acc[mt][nt], (const uint32_t*)&alv[mt], b0, b1);
                }
            }
        }
        __syncthreads();
    }

    float* Cs = sm;
#pragma unroll
    for (int mt = 0; mt < 4; ++mt) {
        int r = wi + mt * 16 + g;
#pragma unroll
        for (int nt = 0; nt < 4; ++nt) {
            int col = wn + nt * 8 + 2 * tg;
            Cs[col * 260 + r]            = acc[mt][nt][0];
            Cs[(col + 1) * 260 + r]      = acc[mt][nt][1];
            Cs[col * 260 + r + 8]        = acc[mt][nt][2];
            Cs[(col + 1) * 260 + r + 8]  = acc[mt][nt][3];
        }
    }
    __syncthreads();
    size_t obase = ((size_t)h * 4096 + nd0) * 512 + i0;
#pragma unroll
    for (int it = 0; it < 16; ++it) {
        int idx = it * 512 + tid;
        int col = idx >> 6, rq = idx & 63;
        *(float4*)(g_o2 + obase + (size_t)col * 512 + rq * 4) =
            *(const float4*)(Cs + col * 260 + rq * 4);
    }
}

// ---------------------------------------------------------------------------
// Kernel 5: out = (g .* o) @ Wout^T
// ---------------------------------------------------------------------------
__global__ __launch_bounds__(256) void out_kernel(
    const float* __restrict__ Wout, float* __restrict__ out)
{
    __shared__ float As[64 * 128];
    __shared__ float Wt[64 * 64];
    int tid = threadIdx.x;
    int n = blockIdx.x & 511, s0 = (blockIdx.x >> 9) * 128;

#pragma unroll
    for (int it = 0; it < 4; ++it) {
        int idx = it * 256 + tid;
        int c = idx & 63, kq = idx >> 6;
        float4 a = *(const float4*)(Wout + c * 64 + kq * 4);
        Wt[(kq * 4 + 0) * 64 + c] = a.x;
        Wt[(kq * 4 + 1) * 64 + c] = a.y;
        Wt[(kq * 4 + 2) * 64 + c] = a.z;
        Wt[(kq * 4 + 3) * 64 + c] = a.w;
    }

#pragma unroll
    for (int it = 0; it < 8; ++it) {
        int idx = it * 256 + tid;
        int c = idx >> 5, sq = idx & 31;
        *(float4*)(As + c * 128 + sq * 4) =
            *(const float4*)(g_o2 + ((size_t)c * 512 + n) * 512 + s0 + sq * 4);
    }
    __syncthreads();
#pragma unroll
    for (int it = 0; it < 8; ++it) {
        int idx = it * 256 + tid;
        int row = idx & 127, q = idx >> 7;
        float4 g4 = *(const float4*)(g_g + ((size_t)(s0 + row) * 512 + n) * CM + q * 4);
        As[(q * 4 + 0) * 128 + row] *= g4.x;
        As[(q * 4 + 1) * 128 + row] *= g4.y;
        As[(q * 4 + 2) * 128 + row] *= g4.z;
        As[(q * 4 + 3) * 128 + row] *= g4.w;
    }
    __syncthreads();

    int tx = tid & 15, ty = tid >> 4;
    float acc[8][4];
#pragma unroll
    for (int r = 0; r < 8; ++r)
#pragma unroll
        for (int c = 0; c < 4; ++c) acc[r][c] = 0.f;

#pragma unroll
    for (int k = 0; k < 64; ++k) {
        float4 a0 = *(const float4*)(As + k * 128 + ty * 4);
        float4 a1 = *(const float4*)(As + k * 128 + 64 + ty * 4);
        float4 w = *(const float4*)(Wt + k * 64 + tx * 4);
        float a[8] = {a0.x, a0.y, a0.z, a0.w, a1.x, a1.y, a1.z, a1.w};
        float wr[4] = {w.x, w.y, w.z, w.w};
#pragma unroll
        for (int r = 0; r < 8; ++r)
#pragma unroll
            for (int c = 0; c < 4; ++c)
                acc[r][c] = fmaf(a[r], wr[c], acc[r][c]);
    }
#pragma unroll
    for (int rh = 0; rh < 2; ++rh)
#pragma unroll
        for (int rr = 0; rr < 4; ++rr) {
            int orow = rh * 64 + ty * 4 + rr;
            float4 v4 = make_float4(acc[rh * 4 + rr][0], acc[rh * 4 + rr][1],
                                    acc[rh * 4 + rr][2], acc[rh * 4 + rr][3]);
            *(float4*)(out + ((size_t)(s0 + orow) * 512 + n) * CM + tx * 4) = v4;
        }
}

// ---------------------------------------------------------------------------
extern "C" void kernel_launch(void* const* d_in, const int* in_sizes, int n_in,
                              void* d_out, int out_size)
{
    const float* m    = (const float*)d_in[0];
    const float* z    = (const float*)d_in[1];
    const float* lnmw = (const float*)d_in[2];
    const float* lnmb = (const float*)d_in[3];
    const float* lnzw = (const float*)d_in[4];
    const float* lnzb = (const float*)d_in[5];
    const float* Wv   = (const float*)d_in[6];
    const float* Wb   = (const float*)d_in[7];
    const float* Wg   = (const float*)d_in[8];
    const float* Wout = (const float*)d_in[9];
    float* out = (float*)d_out;

    cudaFuncSetAttribute(pwa_mma_kernel,
                         cudaFuncAttributeMaxDynamicSharedMemorySize, PW_SMEMB);
    cudaFuncSetAttribute(vg_kernel,
                         cudaFuncAttributeMaxDynamicSharedMemorySize, VG_SMEMB);
    cudaFuncSetAttribute(softmax_kernel,
                         cudaFuncAttributeMaxDynamicSharedMemorySize, SMX_SMEMB);

    bias_ln_kernel<<<SQ * SQ / 32, 256>>>(z, lnzw, lnzb, Wb);
    softmax_kernel<<<(SQ / 16) * NH, 256, SMX_SMEMB>>>();
    vg_kernel<<<dim3(512, 4), 256, VG_SMEMB>>>(m, lnmw, lnmb, Wv, Wg);
    dim3 gD(32, 2, NH);
    pwa_mma_kernel<<<gD, 512, PW_SMEMB>>>();
    out_kernel<<<SQ * NSEQ / 128, 256>>>(Wout, out);
}